// round 4
// baseline (speedup 1.0000x reference)
#include <cuda_runtime.h>
#include <math.h>

// FraudDetectionHybridModel — closed-form quantum-circuit reduction.
// feats(patch) = prefix products of cos(pixel); RZ(patch_params) is pure phase (unused).
// out[b] = sigmoid( cos( sum_{p,w} feats[b,p,w] * W[p*4+w] ) )
//
// R4: coalesced smem staging (R3) at R2's grid shape.
//  CTA = 256 threads = 8 warps, 4 images/CTA, grid = B/4 = 1024 (~7 CTAs/SM).
//  Phase 1: stage 4 images (12544 B) + weights (3136 B) with contiguous float4
//           loads — minimum L1tex wavefronts (4 per LDG.128).
//  Phase 2: warp = half an image (49 two-patch items), LDS.128 reads.

#define THREADS 256
#define IMGS_PER_CTA 4
#define NPAIRS_HALF 49

__device__ __forceinline__ float pair_contrib(const float* __restrict__ im,
                                              const float* __restrict__ sw,
                                              int p)
{
    // item p = (i, c): rows 2i/2i+1, cols 4c..4c+3 = patches (i,2c) and (i,2c+1)
    const int i = p / 7;
    const int c = p - i * 7;
    const float4 top = *reinterpret_cast<const float4*>(im + i * 56 + c * 4);
    const float4 bot = *reinterpret_cast<const float4*>(im + i * 56 + 28 + c * 4);

    const float cA0 = __cosf(top.x), cA1 = __cosf(top.y);
    const float cA2 = __cosf(bot.x), cA3 = __cosf(bot.y);
    const float fA0 = cA0, fA1 = fA0 * cA1, fA2 = fA1 * cA2, fA3 = fA2 * cA3;

    const float cB0 = __cosf(top.z), cB1 = __cosf(top.w);
    const float cB2 = __cosf(bot.z), cB3 = __cosf(bot.w);
    const float fB0 = cB0, fB1 = fB0 * cB1, fB2 = fB1 * cB2, fB3 = fB2 * cB3;

    const int pa = (i * 14 + 2 * c) * 4;
    const float4 wa = *reinterpret_cast<const float4*>(sw + pa);
    const float4 wb = *reinterpret_cast<const float4*>(sw + pa + 4);

    float r = fmaf(fA0, wa.x, fmaf(fA1, wa.y, fmaf(fA2, wa.z, fA3 * wa.w)));
    r = fmaf(fB0, wb.x, fmaf(fB1, wb.y, fmaf(fB2, wb.z, fmaf(fB3, wb.w, r))));
    return r;
}

__global__ void __launch_bounds__(THREADS)
fraud_kernel(const float* __restrict__ x,   // [B, 784]
             const float* __restrict__ w,   // [785]
             float* __restrict__ out,       // [B]
             int B)
{
    __shared__ float simg[IMGS_PER_CTA * 784];   // 12544 B
    __shared__ float sw[784];                    //  3136 B
    __shared__ float wsum[8];

    const int tid  = threadIdx.x;
    const int warp = tid >> 5;
    const int lane = tid & 31;

    int img0 = blockIdx.x * IMGS_PER_CTA;
    if (img0 + IMGS_PER_CTA > B) img0 = B - IMGS_PER_CTA;   // B >= 4; dup work safe

    // ---- Phase 1: perfectly coalesced staging ----
    // 4 images = 784 float4 = 3*256 + 16 ; weights = 196 float4
    const float4* gx = reinterpret_cast<const float4*>(x + (size_t)img0 * 784);
    float4* s4 = reinterpret_cast<float4*>(simg);
    #pragma unroll
    for (int k = 0; k < 3; ++k)
        s4[tid + k * THREADS] = gx[tid + k * THREADS];
    if (tid < 16)
        s4[768 + tid] = gx[768 + tid];
    if (tid < 196)
        reinterpret_cast<float4*>(sw)[tid] = reinterpret_cast<const float4*>(w)[tid];
    __syncthreads();

    // ---- Phase 2: warp = half an image ----
    const float* im = simg + (warp >> 1) * 784;
    const int half = warp & 1;

    const int p0 = half * NPAIRS_HALF + lane;
    float acc = pair_contrib(im, sw, p0);
    if (lane < NPAIRS_HALF - 32)
        acc += pair_contrib(im, sw, p0 + 32);

    #pragma unroll
    for (int off = 16; off > 0; off >>= 1)
        acc += __shfl_xor_sync(0xffffffffu, acc, off);

    if (lane == 0) wsum[warp] = acc;
    __syncthreads();

    if (warp == 0 && lane < IMGS_PER_CTA) {
        const int img = img0 + lane;
        if (img < B) {
            const float a  = wsum[2 * lane] + wsum[2 * lane + 1];
            const float cv = cosf(a);                  // |a| can be ~40: accurate cos
            out[img] = 1.0f / (1.0f + __expf(-cv));
        }
    }
}

extern "C" void kernel_launch(void* const* d_in, const int* in_sizes, int n_in,
                              void* d_out, int out_size)
{
    const float* x = (const float*)d_in[0];   // [B,1,28,28]
    // d_in[1] = patch_params — provably unused (RZ is pure phase)
    const float* w = (const float*)d_in[2];   // [785]
    float* out = (float*)d_out;

    const int B = in_sizes[0] / 784;
    const int grid = (B + IMGS_PER_CTA - 1) / IMGS_PER_CTA;
    fraud_kernel<<<grid, THREADS>>>(x, w, out, B);
}

// round 5
// speedup vs baseline: 1.0257x; 1.0257x over previous
#include <cuda_runtime.h>
#include <math.h>

// FraudDetectionHybridModel — closed-form quantum-circuit reduction.
// feats(patch) = prefix products of cos(pixel); RZ(patch_params) is pure phase (unused).
// out[b] = sigmoid( cos( sum_{p,w} feats[b,p,w] * W[p*4+w] ) )
//
// R5: one WARP per image, zero barriers, zero smem.
//  Image = 98 items (2 rows x 4 cols = 2 adjacent patches, two float4 loads).
//  Lane k owns items k, k+32, k+64 (+ item 96/97 for lanes 0/1).
//  All loads front-batched (MLP ~8), then cos/FMA, then pure-shfl reduce,
//  lane 0 stores. 8 warps/CTA = 8 images, grid = B/8.

#define THREADS 256
#define IMGS_PER_CTA 8

__device__ __forceinline__ float pair_contrib(float4 top, float4 bot, int i, int c,
                                              const float* __restrict__ w)
{
    // patches (i,2c) and (i,2c+1); rows 2i,2i+1; cols 4c..4c+3
    const float cA0 = __cosf(top.x), cA1 = __cosf(top.y);
    const float cA2 = __cosf(bot.x), cA3 = __cosf(bot.y);
    const float fA0 = cA0, fA1 = fA0 * cA1, fA2 = fA1 * cA2, fA3 = fA2 * cA3;

    const float cB0 = __cosf(top.z), cB1 = __cosf(top.w);
    const float cB2 = __cosf(bot.z), cB3 = __cosf(bot.w);
    const float fB0 = cB0, fB1 = fB0 * cB1, fB2 = fB1 * cB2, fB3 = fB2 * cB3;

    const int pa = (i * 14 + 2 * c) * 4;
    const float4 wa = __ldg(reinterpret_cast<const float4*>(w + pa));
    const float4 wb = __ldg(reinterpret_cast<const float4*>(w + pa + 4));

    float r = fmaf(fA0, wa.x, fmaf(fA1, wa.y, fmaf(fA2, wa.z, fA3 * wa.w)));
    r = fmaf(fB0, wb.x, fmaf(fB1, wb.y, fmaf(fB2, wb.z, fmaf(fB3, wb.w, r))));
    return r;
}

__global__ void __launch_bounds__(THREADS)
fraud_kernel(const float* __restrict__ x,   // [B, 784]
             const float* __restrict__ w,   // [785]
             float* __restrict__ out,       // [B]
             int B)
{
    const int warp = threadIdx.x >> 5;
    const int lane = threadIdx.x & 31;

    int img = blockIdx.x * IMGS_PER_CTA + warp;
    const bool live = (img < B);
    if (!live) img = B - 1;                       // duplicate work; store guarded

    const float* im = x + (size_t)img * 784;

    // ---- front-batched load phase: items lane, lane+32, lane+64 (+96/97) ----
    int ii[3], cc[3];
    float4 t[3], bo[3];
    #pragma unroll
    for (int k = 0; k < 3; ++k) {
        const int p = lane + 32 * k;              // 0..95
        ii[k] = p / 7;
        cc[k] = p - ii[k] * 7;
        const float* q = im + ii[k] * 56 + cc[k] * 4;
        t[k]  = __ldg(reinterpret_cast<const float4*>(q));
        bo[k] = __ldg(reinterpret_cast<const float4*>(q + 28));
    }
    const bool tail = (lane < 2);
    float4 t3 = make_float4(0.f,0.f,0.f,0.f), b3 = t3;
    int i3 = 13, c3 = 5 + lane;                   // items 96,97
    if (tail) {
        const float* q = im + i3 * 56 + c3 * 4;
        t3 = __ldg(reinterpret_cast<const float4*>(q));
        b3 = __ldg(reinterpret_cast<const float4*>(q + 28));
    }

    // ---- compute ----
    float acc = pair_contrib(t[0], bo[0], ii[0], cc[0], w);
    acc      += pair_contrib(t[1], bo[1], ii[1], cc[1], w);
    acc      += pair_contrib(t[2], bo[2], ii[2], cc[2], w);
    if (tail)
        acc  += pair_contrib(t3, b3, i3, c3, w);

    // ---- warp-only reduction, no barriers anywhere ----
    #pragma unroll
    for (int off = 16; off > 0; off >>= 1)
        acc += __shfl_xor_sync(0xffffffffu, acc, off);

    if (lane == 0 && live) {
        const float cv = cosf(acc);               // |acc| can be ~40: accurate cos
        out[img] = 1.0f / (1.0f + __expf(-cv));
    }
}

extern "C" void kernel_launch(void* const* d_in, const int* in_sizes, int n_in,
                              void* d_out, int out_size)
{
    const float* x = (const float*)d_in[0];   // [B,1,28,28]
    // d_in[1] = patch_params — provably unused (RZ is pure phase)
    const float* w = (const float*)d_in[2];   // [785]
    float* out = (float*)d_out;

    const int B = in_sizes[0] / 784;
    const int grid = (B + IMGS_PER_CTA - 1) / IMGS_PER_CTA;
    fraud_kernel<<<grid, THREADS>>>(x, w, out, B);
}

// round 6
// speedup vs baseline: 1.0295x; 1.0037x over previous
#include <cuda_runtime.h>
#include <math.h>

// FraudDetectionHybridModel — closed-form quantum-circuit reduction.
// feats(patch) = prefix products of cos(pixel); RZ(patch_params) is pure phase (unused).
// out[b] = sigmoid( cos( sum_{p,w} feats[b,p,w] * W[p*4+w] ) )
//
// R6: coalesced-by-construction lane mapping.
//  CTA = 224 threads = 7 warps = 1 image. Warp w owns rows 4w..4w+3
//  (= patch-rows 2w, 2w+1). Lane L (<28) loads float4 #L of that 448B block:
//  ONE perfectly coalesced LDG.128 per warp for all pixel data.
//    lanes 0-6  : row 4w   (top of patch-row 2w),  cols 4c..4c+3
//    lanes 7-13 : row 4w+1 (bottom of patch-row 2w)
//    lanes 14-20: row 4w+2 (top of patch-row 2w+1)
//    lanes 21-27: row 4w+3 (bottom)
//  Every lane: g0=cos(x), g1=g0*cos(y), h0=cos(z), h1=h0*cos(w).
//  shfl_down(.,7) moves bottom-row (c2, c2*c3) to the matching top lane,
//  which folds both patches' 4-term dot products. Warp-reduce, 1 tiny barrier,
//  thread 0 does cos+sigmoid.

#define THREADS 224

__global__ void __launch_bounds__(THREADS, 9)
fraud_kernel(const float* __restrict__ x,   // [B, 784]
             const float* __restrict__ w,   // [785]
             float* __restrict__ out,       // [B]
             int B)
{
    const int tid  = threadIdx.x;
    const int warp = tid >> 5;               // 0..6
    const int lane = tid & 31;

    const int img = blockIdx.x;
    const float* im = x + (size_t)img * 784;

    // ---- single coalesced pixel load (28 consecutive float4 per warp) ----
    float4 v = make_float4(0.f, 0.f, 0.f, 0.f);
    if (lane < 28)
        v = __ldg(reinterpret_cast<const float4*>(im + warp * 112 + 4 * lane));

    // ---- uniform per-lane trig ----
    const float g0 = __cosf(v.x);
    const float g1 = g0 * __cosf(v.y);       // pair at cols 4c,4c+1
    const float h0 = __cosf(v.z);
    const float h1 = h0 * __cosf(v.w);       // pair at cols 4c+2,4c+3

    // ---- bottom -> top exchange (delta 7 within warp) ----
    const float rg0 = __shfl_down_sync(0xffffffffu, g0, 7);
    const float rg1 = __shfl_down_sync(0xffffffffu, g1, 7);
    const float rh0 = __shfl_down_sync(0xffffffffu, h0, 7);
    const float rh1 = __shfl_down_sync(0xffffffffu, h1, 7);

    // top lanes: 0-6 and 14-20
    const bool top = (lane < 7) || (lane >= 14 && lane < 21);
    float acc = 0.0f;
    if (top) {
        const int pr = 2 * warp + (lane >= 14 ? 1 : 0);   // patch row 0..13
        const int c  = lane % 7;                          // column-pair 0..6
        const int pA = pr * 14 + 2 * c;                   // patch index of A
        const float4 wa = __ldg(reinterpret_cast<const float4*>(w + 4 * pA));
        const float4 wb = __ldg(reinterpret_cast<const float4*>(w + 4 * pA + 4));
        // patch A: f0=g0, f1=g1, f2=g1*rg0, f3=g1*rg1
        acc  = fmaf(g0, wa.x, g1 * fmaf(rg0, wa.z, fmaf(rg1, wa.w, wa.y)));
        // patch B: f0=h0, f1=h1, f2=h1*rh0, f3=h1*rh1
        acc += fmaf(h0, wb.x, h1 * fmaf(rh0, wb.z, fmaf(rh1, wb.w, wb.y)));
    }

    // ---- warp reduce ----
    #pragma unroll
    for (int off = 16; off > 0; off >>= 1)
        acc += __shfl_xor_sync(0xffffffffu, acc, off);

    __shared__ float wsum[7];
    if (lane == 0) wsum[warp] = acc;
    __syncthreads();

    if (tid == 0) {
        float a = wsum[0];
        #pragma unroll
        for (int k = 1; k < 7; ++k) a += wsum[k];
        const float cv = cosf(a);             // |a| can be ~40: accurate cos
        out[img] = 1.0f / (1.0f + __expf(-cv));
    }
}

extern "C" void kernel_launch(void* const* d_in, const int* in_sizes, int n_in,
                              void* d_out, int out_size)
{
    const float* x = (const float*)d_in[0];   // [B,1,28,28]
    // d_in[1] = patch_params — provably unused (RZ is pure phase)
    const float* w = (const float*)d_in[2];   // [785]
    float* out = (float*)d_out;

    const int B = in_sizes[0] / 784;
    fraud_kernel<<<B, THREADS>>>(x, w, out, B);
}

// round 7
// speedup vs baseline: 1.3413x; 1.3029x over previous
#include <cuda_runtime.h>
#include <math.h>

// FraudDetectionHybridModel — closed-form quantum-circuit reduction.
// feats(patch) = prefix products of cos(pixel); RZ(patch_params) is pure phase (unused).
// out[b] = sigmoid( cos( sum_{p,w} feats[b,p,w] * W[p*4+w] ) )
//
// R7 = R2 (best, 6.69us) with a shortened per-CTA critical tail:
//  - fast final cos via 2-term Cody-Waite + __cosf (|angle| <~ 50)
//  - each even warp finalizes its own image (no warp0 serialization)
//  - same layout: warp = half an image (49 two-patch items), grid = B/4 x 256.

#define NPAIRS_HALF 49

__device__ __forceinline__ float pair_contrib(float4 top, float4 bot, int i, int c,
                                              const float* __restrict__ w)
{
    // patches (i,2c) and (i,2c+1); rows 2i,2i+1; cols 4c..4c+3
    const float cA0 = __cosf(top.x), cA1 = __cosf(top.y);
    const float cA2 = __cosf(bot.x), cA3 = __cosf(bot.y);
    const float fA0 = cA0, fA1 = fA0 * cA1, fA2 = fA1 * cA2, fA3 = fA2 * cA3;

    const float cB0 = __cosf(top.z), cB1 = __cosf(top.w);
    const float cB2 = __cosf(bot.z), cB3 = __cosf(bot.w);
    const float fB0 = cB0, fB1 = fB0 * cB1, fB2 = fB1 * cB2, fB3 = fB2 * cB3;

    const int pa = (i * 14 + 2 * c) * 4;
    const float4 wa = __ldg(reinterpret_cast<const float4*>(w + pa));
    const float4 wb = __ldg(reinterpret_cast<const float4*>(w + pa + 4));

    float r = fmaf(fA0, wa.x, fmaf(fA1, wa.y, fmaf(fA2, wa.z, fA3 * wa.w)));
    r = fmaf(fB0, wb.x, fmaf(fB1, wb.y, fmaf(fB2, wb.z, fmaf(fB3, wb.w, r))));
    return r;
}

// accurate-enough cos for |a| <= ~200: Cody-Waite 2-term reduction into
// [-pi,pi], then hardware __cosf. abs err ~1e-6..1e-5 — far inside 1e-3 gate.
__device__ __forceinline__ float fast_cos_mid(float a)
{
    const float INV_2PI = 0.15915493667125702f;
    const float PI2_HI  = 6.28125f;              // exactly representable
    const float PI2_LO  = 1.9353071795864769e-3f;
    const float k = rintf(a * INV_2PI);
    float r = fmaf(-k, PI2_HI, a);
    r = fmaf(-k, PI2_LO, r);
    return __cosf(r);
}

__global__ void __launch_bounds__(256, 8)
fraud_kernel(const float* __restrict__ x,   // [B, 784]
             const float* __restrict__ w,   // [785]
             float* __restrict__ out,       // [B]
             int B)
{
    const int tid  = threadIdx.x;
    const int warp = tid >> 5;
    const int lane = tid & 31;

    int b = blockIdx.x * 4 + (warp >> 1);
    if (b >= B) b = B - 1;                    // safe duplicate work; store is guarded
    const int half = warp & 1;

    const float* xb = x + (size_t)b * 784;

    // ---- front-batched load phase ----
    const int p0 = half * NPAIRS_HALF + lane;  // item 0..97
    const int i0 = p0 / 7, c0 = p0 - i0 * 7;
    const float* q0 = xb + i0 * 56 + c0 * 4;
    const float4 t0 = __ldg(reinterpret_cast<const float4*>(q0));
    const float4 b0 = __ldg(reinterpret_cast<const float4*>(q0 + 28));

    const bool a1 = (lane < NPAIRS_HALF - 32);
    int i1 = 0, c1 = 0;
    float4 t1 = make_float4(0.f, 0.f, 0.f, 0.f), b1 = t1;
    if (a1) {
        const int p1 = p0 + 32;
        i1 = p1 / 7; c1 = p1 - i1 * 7;
        const float* q1 = xb + i1 * 56 + c1 * 4;
        t1 = __ldg(reinterpret_cast<const float4*>(q1));
        b1 = __ldg(reinterpret_cast<const float4*>(q1 + 28));
    }

    // ---- compute ----
    float acc = pair_contrib(t0, b0, i0, c0, w);
    if (a1) acc += pair_contrib(t1, b1, i1, c1, w);

    // ---- warp butterfly reduce ----
    #pragma unroll
    for (int off = 16; off > 0; off >>= 1)
        acc += __shfl_xor_sync(0xffffffffu, acc, off);

    __shared__ float wsum[8];
    if (lane == 0) wsum[warp] = acc;
    __syncthreads();

    // each even warp finalizes its own image — parallel tails, no warp0 gather
    if (lane == 0 && (warp & 1) == 0) {
        const int img = blockIdx.x * 4 + (warp >> 1);
        if (img < B) {
            const float a  = wsum[warp] + wsum[warp + 1];
            const float cv = fast_cos_mid(a);
            out[img] = 1.0f / (1.0f + __expf(-cv));
        }
    }
}

extern "C" void kernel_launch(void* const* d_in, const int* in_sizes, int n_in,
                              void* d_out, int out_size)
{
    const float* x = (const float*)d_in[0];   // [B,1,28,28]
    // d_in[1] = patch_params — provably unused (RZ is pure phase)
    const float* w = (const float*)d_in[2];   // [785]
    float* out = (float*)d_out;

    const int B = in_sizes[0] / 784;
    const int grid = (B + 3) / 4;
    fraud_kernel<<<grid, 256>>>(x, w, out, B);
}